// round 5
// baseline (speedup 1.0000x reference)
#include <cuda_runtime.h>
#include <stdint.h>

#define SLEN  400000
#define WIN   400
#define NW    1000
#define NA    3
#define NR    64
#define NB    2
#define KTOP  8
#define NF4   100
#define NTILES (NA * NW)      // 3000
#define GRID  444             // 148 SMs * 3 CTAs
#define NT_MAX 7
#define RING  3
#define ROWB  1600            // bytes per row-window
#define STAGE_BYTES (8 * ROWB) // 12800: 8 rows per stage

// dynamic smem layout (bytes)
#define OFF_RING  0
#define OFF_SM    (RING * STAGE_BYTES)                 // 38400
#define OFF_SSC   (OFF_SM + NT_MAX * NB * NF4 * 16)    // 60800
#define OFF_MBAR  (OFF_SSC + NT_MAX * NB * NR * 4)     // 64384
#define SMEM_BYTES (OFF_MBAR + 2 * RING * 8 + 16)      // 64448

__device__ __forceinline__ uint32_t smem_u32(const void* p) {
    uint32_t a;
    asm("{ .reg .u64 t; cvta.to.shared.u64 t, %1; cvt.u32.u64 %0, t; }" : "=r"(a) : "l"(p));
    return a;
}
__device__ __forceinline__ void mbar_init(uint32_t a, uint32_t c) {
    asm volatile("mbarrier.init.shared.b64 [%0], %1;" :: "r"(a), "r"(c) : "memory");
}
__device__ __forceinline__ void mbar_expect_tx(uint32_t a, uint32_t tx) {
    asm volatile("mbarrier.arrive.expect_tx.shared.b64 _, [%0], %1;" :: "r"(a), "r"(tx) : "memory");
}
__device__ __forceinline__ void mbar_arrive(uint32_t a) {
    asm volatile("mbarrier.arrive.shared.b64 _, [%0];" :: "r"(a) : "memory");
}
__device__ __forceinline__ void mbar_wait(uint32_t a, uint32_t ph) {
    asm volatile(
        "{\n\t.reg .pred P;\n"
        "W%=:\n\t"
        "mbarrier.try_wait.parity.shared.b64 P, [%0], %1, 0x989680;\n\t"
        "@P bra D%=;\n\t"
        "bra W%=;\n"
        "D%=:\n\t}"
        :: "r"(a), "r"(ph) : "memory");
}
__device__ __forceinline__ void bulk_cp(uint32_t dst, const void* src, uint32_t bytes, uint32_t bar) {
    asm volatile(
        "cp.async.bulk.shared::cluster.global.mbarrier::complete_tx::bytes [%0], [%1], %2, [%3];"
        :: "r"(dst), "l"(src), "r"(bytes), "r"(bar) : "memory");
}

__device__ __forceinline__ float warp_sum(float v) {
#pragma unroll
    for (int o = 16; o; o >>= 1) v += __shfl_xor_sync(0xffffffffu, v, o);
    return v;
}

__device__ __forceinline__ unsigned long long mk_key(float v, int r) {
    unsigned u = __float_as_uint(v);
    u = (u & 0x80000000u) ? ~u : (u | 0x80000000u);
    return (((unsigned long long)u) << 6) | (unsigned long long)(63 - r);
}

__global__ __launch_bounds__(256, 3)
void fused_windowed_topk(const float* __restrict__ mixed,
                         const float* __restrict__ ref,
                         const float* __restrict__ weights,
                         float* __restrict__ out,
                         int out_size) {
    extern __shared__ char sm[];
    float4* s_m  = (float4*)(sm + OFF_SM);    // [NT][NB][NF4]
    float*  s_sc = (float*)(sm + OFF_SSC);    // [NT][NB][NR]
    const uint32_t sbase    = smem_u32(sm);
    const uint32_t ring     = sbase + OFF_RING;
    const uint32_t mb_full  = sbase + OFF_MBAR;
    const uint32_t mb_empty = mb_full + RING * 8;

    const int tid  = threadIdx.x;
    const int warp = tid >> 5;
    const int lane = tid & 31;
    const int bid  = blockIdx.x;
    const int cnt  = (NTILES - bid + GRID - 1) / GRID;   // 6 or 7
    const int S    = cnt * 8;                             // stages

    if (tid == 0) {
#pragma unroll
        for (int r = 0; r < RING; r++) {
            mbar_init(mb_full + r * 8, 1);
            mbar_init(mb_empty + r * 8, 8);
        }
        asm volatile("fence.proxy.async.shared::cta;" ::: "memory");
    }

    // ---- stage mixed windows for all tiles ----
    for (int v = tid; v < cnt * NB * NF4; v += 256) {
        const int i   = v / (NB * NF4);
        const int rem = v % (NB * NF4);
        const int b   = rem / NF4;
        const int j   = rem % NF4;
        const int w   = (bid + i * GRID) / NA;
        s_m[(i * NB + b) * NF4 + j] =
            __ldg((const float4*)(mixed + (size_t)b * SLEN + w * WIN) + j);
    }
    __syncthreads();

    // ---- producer helper (inlined twice) ----
    auto produce = [&](int s) {
        const int slot = s % RING;
        const int k    = s / RING;
        if (k > 0) mbar_wait(mb_empty + slot * 8, (k - 1) & 1);
        mbar_expect_tx(mb_full + slot * 8, STAGE_BYTES);
        const int tile = bid + (s >> 3) * GRID;
        const int a = tile % NA;
        const int w = tile / NA;
        const int j = s & 7;
        const char* src = (const char*)ref +
            (((size_t)a * NR + (size_t)j * 8) * SLEN + (size_t)w * WIN) * 4;
        const uint32_t dst = ring + slot * STAGE_BYTES;
#pragma unroll
        for (int r = 0; r < 8; r++)
            bulk_cp(dst + r * ROWB, src + (size_t)r * SLEN * 4, ROWB, mb_full + slot * 8);
    };

    if (tid == 0)
        for (int s = 0; s < RING && s < S; s++) produce(s);

    // ---- main pipeline: consume stages, no block syncs ----
    for (int s = 0; s < S; s++) {
        const int slot = s % RING;
        const int k    = s / RING;
        mbar_wait(mb_full + slot * 8, k & 1);

        const int i = s >> 3;            // tile slot
        const int j = s & 7;             // row group
        const char* rowp = sm + OFF_RING + slot * STAGE_BYTES + warp * ROWB;
        const float4* mp0 = &s_m[(i * NB + 0) * NF4];
        const float4* mp1 = &s_m[(i * NB + 1) * NF4];

        float s0 = 0.f, s1 = 0.f;
#pragma unroll
        for (int t = 0; t < 3; t++) {
            const int j4 = lane + 32 * t;
            const float4 rv = *(const float4*)(rowp + j4 * 16);
            const float4 m0 = mp0[j4];
            const float4 m1 = mp1[j4];
            s0 += rv.x * m0.x + rv.y * m0.y + rv.z * m0.z + rv.w * m0.w;
            s1 += rv.x * m1.x + rv.y * m1.y + rv.z * m1.z + rv.w * m1.w;
        }
        if (lane < 4) {
            const int j4 = 96 + lane;
            const float4 rv = *(const float4*)(rowp + j4 * 16);
            const float4 m0 = mp0[j4];
            const float4 m1 = mp1[j4];
            s0 += rv.x * m0.x + rv.y * m0.y + rv.z * m0.z + rv.w * m0.w;
            s1 += rv.x * m1.x + rv.y * m1.y + rv.z * m1.z + rv.w * m1.w;
        }
        s0 = warp_sum(s0);
        s1 = warp_sum(s1);
        if (lane == 0) {
            const int rr = j * 8 + warp;
            s_sc[(i * NB + 0) * NR + rr] = s0 * (1.0f / WIN);
            s_sc[(i * NB + 1) * NR + rr] = s1 * (1.0f / WIN);
            mbar_arrive(mb_empty + slot * 8);   // all lanes done (warp_sum synced)
        }
        if (tid == 0 && s + RING < S) produce(s + RING);
    }
    __syncthreads();

    // ---- top-k phase: tasks spread over 8 warps ----
    const bool write_idx = (out_size >= NB * NA * NW * (1 + KTOP));

    for (int task = warp; task < cnt * NB; task += 8) {
        const int i = task >> 1;
        const int b = task & 1;
        const int tile = bid + i * GRID;
        const int a = tile % NA;
        const int w = tile / NA;
        const float* sc = &s_sc[(i * NB + b) * NR];

        unsigned long long k0 = mk_key(sc[lane], lane);
        unsigned long long k1 = mk_key(sc[lane + 32], lane + 32);

        const int base = (b * NA + a) * NW + w;
        float acc = 0.f;
#pragma unroll
        for (int k = 0; k < KTOP; k++) {
            unsigned long long km = (k0 > k1) ? k0 : k1;
#pragma unroll
            for (int o = 16; o; o >>= 1) {
                unsigned long long other = __shfl_xor_sync(0xffffffffu, km, o);
                if (other > km) km = other;
            }
            const int rsel = 63 - (int)(km & 63ull);
            acc += sc[rsel] * __ldg(weights + k);
            if (rsel < 32) {
                if (lane == rsel) k0 = 0ull;
            } else {
                if (lane == rsel - 32) k1 = 0ull;
            }
            if (lane == 0 && write_idx) {
                out[NB * NA * NW + base * KTOP + k] = (float)rsel;
            }
        }
        if (lane == 0) out[base] = acc;
    }
}

extern "C" void kernel_launch(void* const* d_in, const int* in_sizes, int n_in,
                              void* d_out, int out_size) {
    const float* mixed   = (const float*)d_in[0];   // [2, 400000]
    const float* ref     = (const float*)d_in[1];   // [3, 64, 400000]
    const float* weights = (const float*)d_in[2];   // [8, 1]
    float* out = (float*)d_out;

    cudaFuncSetAttribute(fused_windowed_topk,
                         cudaFuncAttributeMaxDynamicSharedMemorySize, SMEM_BYTES);
    fused_windowed_topk<<<GRID, 256, SMEM_BYTES>>>(mixed, ref, weights, out, out_size);
}

// round 6
// speedup vs baseline: 2.1282x; 2.1282x over previous
#include <cuda_runtime.h>
#include <stdint.h>

#define SLEN  400000
#define WIN   400
#define NW    1000
#define NA    3
#define NR    64
#define NB    2
#define KTOP  8
#define NF4   100
#define NTILES (NA * NW)   // 3000
#define GRID  444          // 148 SMs * 3 CTAs
#define NT_MAX 7
#define FULL7 336          // 3000 - 444*6 blocks get 7 tiles

#define CHUNKB 2048        // 4 rows x 512 B
// dynamic smem layout (bytes)
#define OFF_RING 0                                   // 8 warps * 2 * 2048 = 32768
#define OFF_TAIL (8 * 2 * CHUNKB)                    // 8 warps * 2 * 512  =  8192
#define OFF_SM   (OFF_TAIL + 8 * 2 * 512)            // 40960: mixed [NT][NB][NF4] f4
#define OFF_SSC  (OFF_SM + NT_MAX * NB * NF4 * 16)   // 63360: scores [NT][NB][NR]
#define SMEM_BYTES (OFF_SSC + NT_MAX * NB * NR * 4)  // 66944

__device__ __forceinline__ uint32_t smem_u32(const void* p) {
    uint32_t a;
    asm("{ .reg .u64 t; cvta.to.shared.u64 t, %1; cvt.u32.u64 %0, t; }" : "=r"(a) : "l"(p));
    return a;
}
__device__ __forceinline__ void cp16(uint32_t dst, const void* src) {
    asm volatile("cp.async.cg.shared.global [%0], [%1], 16;" :: "r"(dst), "l"(src) : "memory");
}
__device__ __forceinline__ void cp_commit() {
    asm volatile("cp.async.commit_group;" ::: "memory");
}
__device__ __forceinline__ void cp_wait1() {
    asm volatile("cp.async.wait_group 1;" ::: "memory");
}
__device__ __forceinline__ void cp_wait0() {
    asm volatile("cp.async.wait_group 0;" ::: "memory");
}

__device__ __forceinline__ float warp_sum(float v) {
#pragma unroll
    for (int o = 16; o; o >>= 1) v += __shfl_xor_sync(0xffffffffu, v, o);
    return v;
}

__device__ __forceinline__ unsigned long long mk_key(float v, int r) {
    unsigned u = __float_as_uint(v);
    u = (u & 0x80000000u) ? ~u : (u | 0x80000000u);
    return (((unsigned long long)u) << 6) | (unsigned long long)(63 - r);
}

__global__ __launch_bounds__(256, 3)
void fused_windowed_topk(const float* __restrict__ mixed,
                         const float* __restrict__ ref,
                         const float* __restrict__ weights,
                         float* __restrict__ out,
                         int out_size) {
    extern __shared__ char sm[];
    float4* s_m  = (float4*)(sm + OFF_SM);
    float*  s_sc = (float*)(sm + OFF_SSC);
    const uint32_t sbase = smem_u32(sm);

    const int tid  = threadIdx.x;
    const int warp = tid >> 5;
    const int lane = tid & 31;
    const int bid  = blockIdx.x;

    // contiguous-window tiling: first FULL7 blocks own 7 tiles, rest 6
    const int cnt   = (bid < FULL7) ? 7 : 6;
    const int tbase = (bid < FULL7) ? bid * 7 : FULL7 * 7 + (bid - FULL7) * 6;

    // ---- per-warp issue state ----
    int ii = 0, ic = 0, mi = 0;   // tile idx, chunk-in-tile, main-chunk counter
    auto issue_one = [&]() {
        if (ii >= cnt) return;
        const int tile = tbase + ii;
        const int a = tile % NA;
        const int w = tile / NA;
        const char* rbase = (const char*)ref +
            ((size_t)(a * NR + warp * 8) * SLEN + (size_t)w * WIN) * 4;
        if (ic < 6) {
            const int rb = (ic >= 3) ? 4 : 0;
            const int t  = ic - ((ic >= 3) ? 3 : 0);
            const uint32_t dst = sbase + OFF_RING + warp * (2 * CHUNKB)
                               + (mi & 1) * CHUNKB + lane * 16;
#pragma unroll
            for (int q = 0; q < 4; q++)
                cp16(dst + q * 512, rbase + (size_t)(rb + q) * SLEN * 4 + t * 512 + lane * 16);
            mi++;
        } else {
            const uint32_t dst = sbase + OFF_TAIL + warp * 1024 + (ii & 1) * 512 + lane * 16;
            cp16(dst, rbase + (size_t)(lane >> 2) * SLEN * 4 + 1536 + (lane & 3) * 16);
        }
        cp_commit();
        if (++ic == 7) { ic = 0; ii++; }
    };

    // prologue: get 2 chunks in flight before anything else
    issue_one();
    issue_one();

    // ---- stage mixed windows for all my tiles ----
    for (int v = tid; v < cnt * NB * NF4; v += 256) {
        const int i   = v / (NB * NF4);
        const int rem = v % (NB * NF4);
        const int b   = rem / NF4;
        const int j   = rem % NF4;
        const int w   = (tbase + i) / NA;
        s_m[(i * NB + b) * NF4 + j] =
            __ldg((const float4*)(mixed + (size_t)b * SLEN + w * WIN) + j);
    }
    __syncthreads();

    // ---- main pipeline: consume chunks, keep 1-2 chunks always in flight ----
    int mc = 0;   // main-chunk consume counter
    for (int i = 0; i < cnt; i++) {
        const float4* mp0 = &s_m[(i * NB + 0) * NF4];
        const float4* mp1 = &s_m[(i * NB + 1) * NF4];

        float s0[8], s1[8];
#pragma unroll
        for (int rr = 0; rr < 8; rr++) { s0[rr] = 0.f; s1[rr] = 0.f; }

#pragma unroll
        for (int c = 0; c < 6; c++) {
            const int rb = (c >= 3) ? 4 : 0;
            const int t  = c - ((c >= 3) ? 3 : 0);
            cp_wait1();   // oldest pending (this chunk) is done
            const char* buf = sm + OFF_RING + warp * (2 * CHUNKB)
                            + (mc & 1) * CHUNKB + lane * 16;
            const float4 m0 = mp0[lane + 32 * t];
            const float4 m1 = mp1[lane + 32 * t];
#pragma unroll
            for (int q = 0; q < 4; q++) {
                const float4 rv = *(const float4*)(buf + q * 512);
                s0[rb + q] += rv.x * m0.x + rv.y * m0.y + rv.z * m0.z + rv.w * m0.w;
                s1[rb + q] += rv.x * m1.x + rv.y * m1.y + rv.z * m1.z + rv.w * m1.w;
            }
            mc++;
            issue_one();
        }

        // tail chunk (j4 = 96..99, lanes 0-3), cross-lane -> syncwarp
        if (i + 1 == cnt) cp_wait0(); else cp_wait1();
        __syncwarp();
        if (lane < 4) {
            const char* tb = sm + OFF_TAIL + warp * 1024 + (i & 1) * 512;
            const float4 m0 = mp0[96 + lane];
            const float4 m1 = mp1[96 + lane];
#pragma unroll
            for (int rr = 0; rr < 8; rr++) {
                const float4 rv = *(const float4*)(tb + rr * 64 + lane * 16);
                s0[rr] += rv.x * m0.x + rv.y * m0.y + rv.z * m0.z + rv.w * m0.w;
                s1[rr] += rv.x * m1.x + rv.y * m1.y + rv.z * m1.z + rv.w * m1.w;
            }
        }
        issue_one();

        // reduce (identical tree -> bit-identical)
#pragma unroll
        for (int rr = 0; rr < 8; rr++) {
            float t0 = warp_sum(s0[rr]);
            float t1 = warp_sum(s1[rr]);
            if (lane == 0) {
                s_sc[(i * NB + 0) * NR + warp * 8 + rr] = t0 * (1.0f / WIN);
                s_sc[(i * NB + 1) * NR + warp * 8 + rr] = t1 * (1.0f / WIN);
            }
        }
    }
    __syncthreads();

    // ---- top-k phase: tasks spread over 8 warps ----
    const bool write_idx = (out_size >= NB * NA * NW * (1 + KTOP));

    for (int task = warp; task < cnt * NB; task += 8) {
        const int i = task >> 1;
        const int b = task & 1;
        const int tile = tbase + i;
        const int a = tile % NA;
        const int w = tile / NA;
        const float* sc = &s_sc[(i * NB + b) * NR];

        unsigned long long k0 = mk_key(sc[lane], lane);
        unsigned long long k1 = mk_key(sc[lane + 32], lane + 32);

        const int base = (b * NA + a) * NW + w;
        float acc = 0.f;
#pragma unroll
        for (int k = 0; k < KTOP; k++) {
            unsigned long long km = (k0 > k1) ? k0 : k1;
#pragma unroll
            for (int o = 16; o; o >>= 1) {
                unsigned long long other = __shfl_xor_sync(0xffffffffu, km, o);
                if (other > km) km = other;
            }
            const int rsel = 63 - (int)(km & 63ull);
            acc += sc[rsel] * __ldg(weights + k);
            if (rsel < 32) {
                if (lane == rsel) k0 = 0ull;
            } else {
                if (lane == rsel - 32) k1 = 0ull;
            }
            if (lane == 0 && write_idx) {
                out[NB * NA * NW + base * KTOP + k] = (float)rsel;
            }
        }
        if (lane == 0) out[base] = acc;
    }
}

extern "C" void kernel_launch(void* const* d_in, const int* in_sizes, int n_in,
                              void* d_out, int out_size) {
    const float* mixed   = (const float*)d_in[0];   // [2, 400000]
    const float* ref     = (const float*)d_in[1];   // [3, 64, 400000]
    const float* weights = (const float*)d_in[2];   // [8, 1]
    float* out = (float*)d_out;

    cudaFuncSetAttribute(fused_windowed_topk,
                         cudaFuncAttributeMaxDynamicSharedMemorySize, SMEM_BYTES);
    fused_windowed_topk<<<GRID, 256, SMEM_BYTES>>>(mixed, ref, weights, out, out_size);
}